// round 16
// baseline (speedup 1.0000x reference)
#include <cuda_runtime.h>
#include <cuda_fp16.h>
#include <cstdint>
#include <math.h>

#define Bv 4
#define Sv 4096
#define Dv 1024
#define MROWS (Bv*Sv)          // 16384
#define CHUNKS 32
#define CLEN (Sv/CHUNKS)       // 128

// ---------------- scratch (allocation-free: device globals) ----------------
__device__ float  g_omega[(size_t)MROWS * Dv];        // 64 MB fp32
__device__ __half g_ctxh [(size_t)MROWS * 4 * Dv];    // 128 MB half (ctx, LN in-place)
__device__ __half g_h1h  [(size_t)MROWS * 2 * Dv];    // 64 MB half
__device__ float  g_s1 [Bv*CHUNKS*Dv];
__device__ float  g_s2r[Bv*CHUNKS*Dv];
__device__ float  g_s2i[Bv*CHUNKS*Dv];
// half operand copies
__device__ __half g_xh  [(size_t)MROWS * Dv];         // 32 MB
__device__ __half g_w0h [(size_t)Dv * Dv];            // 2 MB
__device__ __half g_w1h [(size_t)4*Dv * 2*Dv];        // 16 MB
__device__ __half g_w2h [(size_t)2*Dv * Dv];          // 4 MB

// ---------------- helpers ----------------
__device__ __forceinline__ float gelu_exact(float v){
    return 0.5f * v * (1.0f + erff(v * 0.70710678118654752f));
}

__device__ __forceinline__ void ldsm_x4(uint32_t& r0, uint32_t& r1, uint32_t& r2, uint32_t& r3,
                                        uint32_t addr){
    asm volatile("ldmatrix.sync.aligned.m8n8.x4.shared.b16 {%0,%1,%2,%3}, [%4];"
        : "=r"(r0), "=r"(r1), "=r"(r2), "=r"(r3) : "r"(addr));
}
__device__ __forceinline__ void ldsm_x4_t(uint32_t& r0, uint32_t& r1, uint32_t& r2, uint32_t& r3,
                                          uint32_t addr){
    asm volatile("ldmatrix.sync.aligned.m8n8.x4.trans.shared.b16 {%0,%1,%2,%3}, [%4];"
        : "=r"(r0), "=r"(r1), "=r"(r2), "=r"(r3) : "r"(addr));
}
__device__ __forceinline__ void mma_f16(float c[4], const uint32_t a[4], const uint32_t b[2]){
    asm volatile(
        "mma.sync.aligned.m16n8k16.row.col.f32.f16.f16.f32 "
        "{%0,%1,%2,%3},{%4,%5,%6,%7},{%8,%9},{%0,%1,%2,%3};\n"
        : "+f"(c[0]), "+f"(c[1]), "+f"(c[2]), "+f"(c[3])
        : "r"(a[0]), "r"(a[1]), "r"(a[2]), "r"(a[3]), "r"(b[0]), "r"(b[1]));
}

// ---------------- fp32 -> fp16 convert (float4 -> 4 halfs) -------------------
__global__ __launch_bounds__(256)
void k_tohalf(const float* __restrict__ in, __half* __restrict__ out, int n4)
{
    int i = blockIdx.x * blockDim.x + threadIdx.x;
    if (i >= n4) return;
    float4 v = ((const float4*)in)[i];
    __half2 h0 = __floats2half2_rn(v.x, v.y);
    __half2 h1 = __floats2half2_rn(v.z, v.w);
    uint2 u; u.x = *(uint32_t*)&h0; u.y = *(uint32_t*)&h1;
    ((uint2*)out)[i] = u;
}

// ---------------- fp16 GEMM: 3-stage cp.async, m16n8k16, 256 threads ---------
// (R13 configuration — best measured GEMM path)
// Block tile 128x128x64, 8 warps as 2x4 (warp tile 64x32), per warp 4x4 mma
// tiles per k16 step. EPI: 0 = bias -> fp32 out; 1 = bias + exact GELU -> half
// out; 2 = bias + fp32 residual -> fp32 out.
#define GSTAGES 3
#define A_STRIDE 72              // 64 + 8 halfs
#define B_STRIDE 136             // 128 + 8 halfs
#define A_BYTES (128*A_STRIDE*2) // 18432
#define B_BYTES (64*B_STRIDE*2)  // 17408
#define GEMM_SMEM (GSTAGES*(A_BYTES+B_BYTES))   // 107520

template<int EPI>
__global__ __launch_bounds__(256, 2)
void k_gemmh(const __half* __restrict__ A, const __half* __restrict__ Bm,
             const float* __restrict__ bias, const float* __restrict__ resid,
             void* __restrict__ Cout, int M, int N, int K)
{
    extern __shared__ char smc[];
    const uint32_t smb = (uint32_t)__cvta_generic_to_shared(smc);

    const int tid  = threadIdx.x;
    const int lane = tid & 31;
    const int w    = tid >> 5;      // 0..7
    const int wr   = w >> 2;        // 0..1
    const int wc   = w & 3;         // 0..3
    const int g    = lane >> 2;     // 0..7
    const int tig  = lane & 3;      // 0..3
    const int m0   = blockIdx.y * 128;
    const int n0   = blockIdx.x * 128;

    // ldmatrix per-lane selectors
    const int a_rsel = lane & 15;            // row within m16 tile
    const int a_koff = (lane >> 4) << 3;     // 0 or 8 (k offset)
    const int b_row  = ((lane >> 3) & 1) * 8 + (lane & 7);
    const int b_coff = (lane >> 4) << 3;     // 0 or 8 (n offset)

    float acc[4][4][4];
#pragma unroll
    for (int i=0;i<4;i++)
#pragma unroll
        for (int j=0;j<4;j++)
#pragma unroll
            for (int k=0;k<4;k++) acc[i][j][k] = 0.f;

    // cp.async loaders: A tile 128x64 halfs (8 chunks/row), B tile 64x128 (16/row)
    auto issue_stage = [&](int s, int kb){
        uint32_t adst0 = smb + (uint32_t)(s*A_BYTES);
#pragma unroll
        for (int i=0; i<4; i++){
            int c = tid + i*256;
            int row = c >> 3, col8 = (c & 7) * 8;
            uint32_t d = adst0 + (uint32_t)(row*A_STRIDE + col8)*2;
            const __half* src = A + (size_t)(m0 + row)*K + kb + col8;
            asm volatile("cp.async.cg.shared.global [%0], [%1], 16;\n" :: "r"(d), "l"(src));
        }
        uint32_t bdst0 = smb + (uint32_t)(GSTAGES*A_BYTES + s*B_BYTES);
#pragma unroll
        for (int i=0; i<4; i++){
            int c = tid + i*256;
            int row = c >> 4, col8 = (c & 15) * 8;
            uint32_t d = bdst0 + (uint32_t)(row*B_STRIDE + col8)*2;
            const __half* src = Bm + (size_t)(kb + row)*N + n0 + col8;
            asm volatile("cp.async.cg.shared.global [%0], [%1], 16;\n" :: "r"(d), "l"(src));
        }
        asm volatile("cp.async.commit_group;\n");
    };

    const int KT = K >> 6;
    issue_stage(0, 0);
    issue_stage(1, 64);

    int st = 0;
    for (int kt = 0; kt < KT; kt++){
        asm volatile("cp.async.wait_group 1;\n" ::: "memory");
        __syncthreads();
        if (kt + 2 < KT){
            int s2 = st + 2; if (s2 >= GSTAGES) s2 -= GSTAGES;
            issue_stage(s2, (kt + 2) * 64);
        } else {
            asm volatile("cp.async.commit_group;\n");   // keep group count uniform
        }

        const uint32_t stA = smb + (uint32_t)(st*A_BYTES);
        const uint32_t stB = smb + (uint32_t)(GSTAGES*A_BYTES + st*B_BYTES);

#pragma unroll
        for (int ks=0; ks<4; ks++){
            const int k0 = ks*16;
            uint32_t af[4][4], bf[4][2];
#pragma unroll
            for (int mt=0; mt<4; mt++){
                uint32_t addr = stA + (uint32_t)((wr*64 + mt*16 + a_rsel)*A_STRIDE + k0 + a_koff)*2;
                ldsm_x4(af[mt][0], af[mt][1], af[mt][2], af[mt][3], addr);
            }
#pragma unroll
            for (int p=0; p<2; p++){
                uint32_t addr = stB + (uint32_t)((k0 + b_row)*B_STRIDE + wc*32 + p*16 + b_coff)*2;
                ldsm_x4_t(bf[2*p][0], bf[2*p][1], bf[2*p+1][0], bf[2*p+1][1], addr);
            }
#pragma unroll
            for (int mt=0; mt<4; mt++)
#pragma unroll
                for (int nt=0; nt<4; nt++)
                    mma_f16(acc[mt][nt], af[mt], bf[nt]);
        }
        // single barrier per tile: stage st is only overwritten by the issue
        // after NEXT iteration's barrier.
        st++; if (st >= GSTAGES) st = 0;
    }

    // epilogue
#pragma unroll
    for (int mt=0; mt<4; mt++){
#pragma unroll
        for (int nt=0; nt<4; nt++){
            int r  = m0 + wr*64 + mt*16 + g;
            int cc = n0 + wc*32 + nt*8 + tig*2;
            float bx = bias[cc], by = bias[cc+1];
#pragma unroll
            for (int h=0; h<2; h++){
                int row = r + 8*h;
                float v0 = acc[mt][nt][2*h+0] + bx;
                float v1 = acc[mt][nt][2*h+1] + by;
                if (EPI == 1){
                    v0 = gelu_exact(v0); v1 = gelu_exact(v1);
                    __half2 hv = __floats2half2_rn(v0, v1);
                    *(uint32_t*)((__half*)Cout + (size_t)row*N + cc) = *(uint32_t*)&hv;
                } else {
                    if (EPI == 2){
                        const float2 rr = *(const float2*)(resid + (size_t)row*N + cc);
                        v0 += rr.x; v1 += rr.y;
                    }
                    float2 o; o.x = v0; o.y = v1;
                    *(float2*)((float*)Cout + (size_t)row*N + cc) = o;
                }
            }
        }
    }
}

// ---------------- scan pass 1: per-chunk sums of omega_scaled ----------------
__global__ __launch_bounds__(256)
void k_chunk_omega(const float* __restrict__ omega, const float* __restrict__ log_scale)
{
    int d = blockIdx.x * blockDim.x + threadIdx.x;
    int c = blockIdx.y, b = blockIdx.z;
    int t0 = c * CLEN;
    const float* p = omega + (size_t)(b*Sv + t0)*Dv + d;
    float sum = 0.f;
#pragma unroll 4
    for (int i=0; i<CLEN; i++)
        sum += p[(size_t)i*Dv] * rsqrtf((float)(t0 + i + 1));
    g_s1[(b*CHUNKS + c)*Dv + d] = sum * expf(log_scale[d]);
}

// ---------------- scan pass 2: phi, sincos, content (half out), chunk sums ---
__global__ __launch_bounds__(256)
void k_phase(const float* __restrict__ x, const float* __restrict__ omega,
             const float* __restrict__ log_scale)
{
    int d = blockIdx.x * blockDim.x + threadIdx.x;
    int c = blockIdx.y, b = blockIdx.z;
    float sc = expf(log_scale[d]);
    float phi = 0.f;
    for (int cp = 0; cp < c; cp++)
        phi += g_s1[(b*CHUNKS + cp)*Dv + d];
    int t0 = c * CLEN;
    size_t base  = (size_t)(b*Sv + t0)*Dv + d;
    size_t base4 = (size_t)(b*Sv + t0)*(4*Dv) + d;
    float sumR = 0.f, sumI = 0.f;
    for (int i=0; i<CLEN; i++){
        float om = omega[base + (size_t)i*Dv];
        phi += om * sc * rsqrtf((float)(t0 + i + 1));
        float s, cv; __sincosf(phi, &s, &cv);
        float xv = x[base + (size_t)i*Dv];
        float cr = xv*cv, ci = xv*s;
        sumR += cr; sumI += ci;
        g_ctxh[base4 + (size_t)i*4*Dv       ] = __float2half_rn(cr);
        g_ctxh[base4 + (size_t)i*4*Dv +  Dv ] = __float2half_rn(ci);
    }
    g_s2r[(b*CHUNKS + c)*Dv + d] = sumR;
    g_s2i[(b*CHUNKS + c)*Dv + d] = sumI;
}

// ---------------- scan pass 3: running memory + retrieved (half out) ---------
__global__ __launch_bounds__(256)
void k_retrieve(const float* __restrict__ x, const float* __restrict__ omega,
                const float* __restrict__ log_scale)
{
    int d = blockIdx.x * blockDim.x + threadIdx.x;
    int c = blockIdx.y, b = blockIdx.z;
    float sc = expf(log_scale[d]);
    float phi = 0.f, aR = 0.f, aI = 0.f;
    for (int cp = 0; cp < c; cp++){
        int si = (b*CHUNKS + cp)*Dv + d;
        phi += g_s1[si];
        aR  += g_s2r[si];
        aI  += g_s2i[si];
    }
    int t0 = c * CLEN;
    size_t base  = (size_t)(b*Sv + t0)*Dv + d;
    size_t base4 = (size_t)(b*Sv + t0)*(4*Dv) + d;
    for (int i=0; i<CLEN; i++){
        float om = omega[base + (size_t)i*Dv];
        phi += om * sc * rsqrtf((float)(t0 + i + 1));
        float s, cv; __sincosf(phi, &s, &cv);
        float xv = x[base + (size_t)i*Dv];
        float cr = xv*cv, ci = xv*s;
        aR += cr; aI += ci;
        float inv = 1.0f / (float)(t0 + i + 1);
        float mr = aR*inv, mi = aI*inv;
        g_ctxh[base4 + (size_t)i*4*Dv + 2*Dv] = __float2half_rn(mr*cv + mi*s);
        g_ctxh[base4 + (size_t)i*4*Dv + 3*Dv] = __float2half_rn(mi*cv - mr*s);
    }
}

// ---------------- layernorm over 4096 features, half in-place ----------------
__global__ __launch_bounds__(256)
void k_layernorm_h(const float* __restrict__ gamma, const float* __restrict__ beta,
                   __half* __restrict__ ctx)
{
    const int F = 4*Dv;
    __half* p = ctx + (size_t)blockIdx.x * F;
    const int tid = threadIdx.x;

    // 16 halfs per thread: two uint4 loads (indices tid, tid+256)
    uint4 u0 = ((const uint4*)p)[tid];
    uint4 u1 = ((const uint4*)p)[tid + 256];
    float v[16];
    {
        uint32_t uu[8] = {u0.x,u0.y,u0.z,u0.w, u1.x,u1.y,u1.z,u1.w};
#pragma unroll
        for (int k=0; k<8; k++){
            __half2 h = *(__half2*)&uu[k];
            float2 f = __half22float2(h);
            v[2*k] = f.x; v[2*k+1] = f.y;
        }
    }
    float s = 0.f, q = 0.f;
#pragma unroll
    for (int k=0; k<16; k++){ s += v[k]; q += v[k]*v[k]; }
#pragma unroll
    for (int o=16; o>0; o>>=1){
        s += __shfl_xor_sync(0xffffffffu, s, o);
        q += __shfl_xor_sync(0xffffffffu, q, o);
    }
    __shared__ float ss[8], qq[8];
    int lane = tid & 31, wid = tid >> 5;
    if (lane == 0){ ss[wid] = s; qq[wid] = q; }
    __syncthreads();
    if (tid == 0){
        float ts = 0.f, tq = 0.f;
        for (int i=0;i<8;i++){ ts += ss[i]; tq += qq[i]; }
        ss[0] = ts; qq[0] = tq;
    }
    __syncthreads();
    float mu  = ss[0] * (1.0f / F);
    float var = qq[0] * (1.0f / F) - mu*mu;
    float rs  = rsqrtf(var + 1e-5f);

    // normalize + gamma/beta, write back half
#pragma unroll
    for (int half_idx = 0; half_idx < 2; half_idx++){
        int base = (tid + half_idx*256) * 8;     // feature index of first of 8
        uint32_t outw[4];
#pragma unroll
        for (int k=0; k<4; k++){
            int fi = base + 2*k;
            float g0 = gamma[fi], g1 = gamma[fi+1];
            float b0 = beta[fi],  b1 = beta[fi+1];
            float x0 = (v[half_idx*8 + 2*k  ] - mu)*rs*g0 + b0;
            float x1 = (v[half_idx*8 + 2*k+1] - mu)*rs*g1 + b1;
            __half2 h = __floats2half2_rn(x0, x1);
            outw[k] = *(uint32_t*)&h;
        }
        uint4 o; o.x = outw[0]; o.y = outw[1]; o.z = outw[2]; o.w = outw[3];
        ((uint4*)p)[tid + half_idx*256] = o;
    }
}

// ---------------- launch ----------------------------------------------------
extern "C" void kernel_launch(void* const* d_in, const int* in_sizes, int n_in,
                              void* d_out, int out_size)
{
    (void)in_sizes; (void)n_in; (void)out_size;
    const float* x         = (const float*)d_in[0];
    const float* W_omega   = (const float*)d_in[1];
    const float* b_omega   = (const float*)d_in[2];
    const float* log_scale = (const float*)d_in[3];
    const float* ln_gamma  = (const float*)d_in[4];
    const float* ln_beta   = (const float*)d_in[5];
    const float* W1        = (const float*)d_in[6];
    const float* b1        = (const float*)d_in[7];
    const float* W2        = (const float*)d_in[8];
    const float* b2        = (const float*)d_in[9];
    float* out = (float*)d_out;

    void* p;
    cudaGetSymbolAddress(&p, g_omega); float*  omega = (float*)p;
    cudaGetSymbolAddress(&p, g_ctxh);  __half* ctxh  = (__half*)p;
    cudaGetSymbolAddress(&p, g_h1h);   __half* h1h   = (__half*)p;
    cudaGetSymbolAddress(&p, g_xh);    __half* xh    = (__half*)p;
    cudaGetSymbolAddress(&p, g_w0h);   __half* w0h   = (__half*)p;
    cudaGetSymbolAddress(&p, g_w1h);   __half* w1h   = (__half*)p;
    cudaGetSymbolAddress(&p, g_w2h);   __half* w2h   = (__half*)p;

    static bool attr_done = false;
    if (!attr_done){
        cudaFuncSetAttribute(k_gemmh<0>, cudaFuncAttributeMaxDynamicSharedMemorySize, GEMM_SMEM);
        cudaFuncSetAttribute(k_gemmh<1>, cudaFuncAttributeMaxDynamicSharedMemorySize, GEMM_SMEM);
        cudaFuncSetAttribute(k_gemmh<2>, cudaFuncAttributeMaxDynamicSharedMemorySize, GEMM_SMEM);
        attr_done = true;
    }

    dim3 blk256(256);

    // convert GEMM operands to fp16
    {
        int n4;
        n4 = (MROWS*Dv)/4;     k_tohalf<<<(n4+255)/256, blk256>>>(x,       xh,  n4);
        n4 = (Dv*Dv)/4;        k_tohalf<<<(n4+255)/256, blk256>>>(W_omega, w0h, n4);
        n4 = (4*Dv*2*Dv)/4;    k_tohalf<<<(n4+255)/256, blk256>>>(W1,      w1h, n4);
        n4 = (2*Dv*Dv)/4;      k_tohalf<<<(n4+255)/256, blk256>>>(W2,      w2h, n4);
    }

    // GEMM1: omega = xh @ w0h + b_omega   (16384 x 1024 x 1024) -> fp32
    dim3 gg1(Dv/128, MROWS/128);
    k_gemmh<0><<<gg1, blk256, GEMM_SMEM>>>(xh, w0h, b_omega, nullptr, omega, MROWS, Dv, Dv);

    // phase / memory scans (chunked two-level scan, fp32 math, half ctx out)
    dim3 gs(Dv/256, CHUNKS, Bv);
    k_chunk_omega<<<gs, blk256>>>(omega, log_scale);
    k_phase     <<<gs, blk256>>>(x, omega, log_scale);
    k_retrieve  <<<gs, blk256>>>(x, omega, log_scale);

    // layernorm in place on half ctx
    k_layernorm_h<<<MROWS, blk256>>>(ln_gamma, ln_beta, ctxh);

    // GEMM2: h1h = gelu(ctxh @ w1h + b1)  (16384 x 2048 x 4096) -> half
    dim3 gg2((2*Dv)/128, MROWS/128);
    k_gemmh<1><<<gg2, blk256, GEMM_SMEM>>>(ctxh, w1h, b1, nullptr, h1h, MROWS, 2*Dv, 4*Dv);

    // GEMM3: out = h1h @ w2h + b2 + x     (16384 x 1024 x 2048) -> fp32
    dim3 gg3(Dv/128, MROWS/128);
    k_gemmh<2><<<gg3, blk256, GEMM_SMEM>>>(h1h, w2h, b2, x, out, MROWS, Dv, 2*Dv);
}

// round 17
// speedup vs baseline: 1.0682x; 1.0682x over previous
#include <cuda_runtime.h>
#include <cuda_fp16.h>
#include <cstdint>
#include <math.h>

#define Bv 4
#define Sv 4096
#define Dv 1024
#define MROWS (Bv*Sv)          // 16384
#define CHUNKS 64
#define CLEN (Sv/CHUNKS)       // 64

// ---------------- scratch (allocation-free: device globals) ----------------
__device__ float  g_omega[(size_t)MROWS * Dv];        // 64 MB fp32
__device__ float  g_ctx  [(size_t)MROWS * 4 * Dv];    // 256 MB fp32 (pre-LN)
__device__ __half g_ctxh [(size_t)MROWS * 4 * Dv];    // 128 MB half (post-LN)
__device__ __half g_h1h  [(size_t)MROWS * 2 * Dv];    // 64 MB half
__device__ float  g_s1  [Bv*CHUNKS*Dv];
__device__ float  g_s1p [Bv*CHUNKS*Dv];
__device__ float  g_s2r [Bv*CHUNKS*Dv];
__device__ float  g_s2i [Bv*CHUNKS*Dv];
__device__ float  g_s2rp[Bv*CHUNKS*Dv];
__device__ float  g_s2ip[Bv*CHUNKS*Dv];
// half operand copies
__device__ __half g_xh  [(size_t)MROWS * Dv];         // 32 MB
__device__ __half g_w0h [(size_t)Dv * Dv];            // 2 MB
__device__ __half g_w1h [(size_t)4*Dv * 2*Dv];        // 16 MB
__device__ __half g_w2h [(size_t)2*Dv * Dv];          // 4 MB

// ---------------- helpers ----------------
__device__ __forceinline__ float gelu_exact(float v){
    return 0.5f * v * (1.0f + erff(v * 0.70710678118654752f));
}

__device__ __forceinline__ void ldsm_x4(uint32_t& r0, uint32_t& r1, uint32_t& r2, uint32_t& r3,
                                        uint32_t addr){
    asm volatile("ldmatrix.sync.aligned.m8n8.x4.shared.b16 {%0,%1,%2,%3}, [%4];"
        : "=r"(r0), "=r"(r1), "=r"(r2), "=r"(r3) : "r"(addr));
}
__device__ __forceinline__ void ldsm_x4_t(uint32_t& r0, uint32_t& r1, uint32_t& r2, uint32_t& r3,
                                          uint32_t addr){
    asm volatile("ldmatrix.sync.aligned.m8n8.x4.trans.shared.b16 {%0,%1,%2,%3}, [%4];"
        : "=r"(r0), "=r"(r1), "=r"(r2), "=r"(r3) : "r"(addr));
}
__device__ __forceinline__ void mma_f16(float c[4], const uint32_t a[4], const uint32_t b[2]){
    asm volatile(
        "mma.sync.aligned.m16n8k16.row.col.f32.f16.f16.f32 "
        "{%0,%1,%2,%3},{%4,%5,%6,%7},{%8,%9},{%0,%1,%2,%3};\n"
        : "+f"(c[0]), "+f"(c[1]), "+f"(c[2]), "+f"(c[3])
        : "r"(a[0]), "r"(a[1]), "r"(a[2]), "r"(a[3]), "r"(b[0]), "r"(b[1]));
}

// ---------------- fp32 -> fp16 convert (float4 -> 4 halfs) -------------------
__global__ __launch_bounds__(256)
void k_tohalf(const float* __restrict__ in, __half* __restrict__ out, int n4)
{
    int i = blockIdx.x * blockDim.x + threadIdx.x;
    if (i >= n4) return;
    float4 v = ((const float4*)in)[i];
    __half2 h0 = __floats2half2_rn(v.x, v.y);
    __half2 h1 = __floats2half2_rn(v.z, v.w);
    uint2 u; u.x = *(uint32_t*)&h0; u.y = *(uint32_t*)&h1;
    ((uint2*)out)[i] = u;
}

// ---------------- fp16 GEMM (R13 config): 3-stage cp.async, m16n8k16 ---------
// Block tile 128x128x64, 8 warps as 2x4 (warp tile 64x32).
// EPI: 0 = bias -> fp32; 1 = bias + exact GELU -> half; 2 = bias + resid ->
// fp32; 3 = bias -> fp32 AND rsqrt-weighted 64-row chunk column sums * exp(lsc)
// into s1out (GEMM1 only; kills k_chunk_omega).
#define GSTAGES 3
#define A_STRIDE 72
#define B_STRIDE 136
#define A_BYTES (128*A_STRIDE*2)
#define B_BYTES (64*B_STRIDE*2)
#define GEMM_SMEM (GSTAGES*(A_BYTES+B_BYTES))   // 107520

template<int EPI>
__global__ __launch_bounds__(256, 2)
void k_gemmh(const __half* __restrict__ A, const __half* __restrict__ Bm,
             const float* __restrict__ bias, const float* __restrict__ resid,
             void* __restrict__ Cout, int M, int N, int K,
             float* __restrict__ s1out, const float* __restrict__ lsc)
{
    extern __shared__ char smc[];
    const uint32_t smb = (uint32_t)__cvta_generic_to_shared(smc);

    const int tid  = threadIdx.x;
    const int lane = tid & 31;
    const int w    = tid >> 5;      // 0..7
    const int wr   = w >> 2;        // 0..1
    const int wc   = w & 3;         // 0..3
    const int g    = lane >> 2;     // 0..7
    const int tig  = lane & 3;      // 0..3
    const int m0   = blockIdx.y * 128;
    const int n0   = blockIdx.x * 128;

    const int a_rsel = lane & 15;
    const int a_koff = (lane >> 4) << 3;
    const int b_row  = ((lane >> 3) & 1) * 8 + (lane & 7);
    const int b_coff = (lane >> 4) << 3;

    float acc[4][4][4];
#pragma unroll
    for (int i=0;i<4;i++)
#pragma unroll
        for (int j=0;j<4;j++)
#pragma unroll
            for (int k=0;k<4;k++) acc[i][j][k] = 0.f;

    auto issue_stage = [&](int s, int kb){
        uint32_t adst0 = smb + (uint32_t)(s*A_BYTES);
#pragma unroll
        for (int i=0; i<4; i++){
            int c = tid + i*256;
            int row = c >> 3, col8 = (c & 7) * 8;
            uint32_t d = adst0 + (uint32_t)(row*A_STRIDE + col8)*2;
            const __half* src = A + (size_t)(m0 + row)*K + kb + col8;
            asm volatile("cp.async.cg.shared.global [%0], [%1], 16;\n" :: "r"(d), "l"(src));
        }
        uint32_t bdst0 = smb + (uint32_t)(GSTAGES*A_BYTES + s*B_BYTES);
#pragma unroll
        for (int i=0; i<4; i++){
            int c = tid + i*256;
            int row = c >> 4, col8 = (c & 15) * 8;
            uint32_t d = bdst0 + (uint32_t)(row*B_STRIDE + col8)*2;
            const __half* src = Bm + (size_t)(kb + row)*N + n0 + col8;
            asm volatile("cp.async.cg.shared.global [%0], [%1], 16;\n" :: "r"(d), "l"(src));
        }
        asm volatile("cp.async.commit_group;\n");
    };

    const int KT = K >> 6;
    issue_stage(0, 0);
    issue_stage(1, 64);

    int st = 0;
    for (int kt = 0; kt < KT; kt++){
        asm volatile("cp.async.wait_group 1;\n" ::: "memory");
        __syncthreads();
        if (kt + 2 < KT){
            int s2 = st + 2; if (s2 >= GSTAGES) s2 -= GSTAGES;
            issue_stage(s2, (kt + 2) * 64);
        } else {
            asm volatile("cp.async.commit_group;\n");
        }

        const uint32_t stA = smb + (uint32_t)(st*A_BYTES);
        const uint32_t stB = smb + (uint32_t)(GSTAGES*A_BYTES + st*B_BYTES);

#pragma unroll
        for (int ks=0; ks<4; ks++){
            const int k0 = ks*16;
            uint32_t af[4][4], bf[4][2];
#pragma unroll
            for (int mt=0; mt<4; mt++){
                uint32_t addr = stA + (uint32_t)((wr*64 + mt*16 + a_rsel)*A_STRIDE + k0 + a_koff)*2;
                ldsm_x4(af[mt][0], af[mt][1], af[mt][2], af[mt][3], addr);
            }
#pragma unroll
            for (int p=0; p<2; p++){
                uint32_t addr = stB + (uint32_t)((k0 + b_row)*B_STRIDE + wc*32 + p*16 + b_coff)*2;
                ldsm_x4_t(bf[2*p][0], bf[2*p][1], bf[2*p+1][0], bf[2*p+1][1], addr);
            }
#pragma unroll
            for (int mt=0; mt<4; mt++)
#pragma unroll
                for (int nt=0; nt<4; nt++)
                    mma_f16(acc[mt][nt], af[mt], bf[nt]);
        }
        st++; if (st >= GSTAGES) st = 0;
    }

    // epilogue
    float s1loc[4][2];
    if (EPI == 3){
#pragma unroll
        for (int nt=0; nt<4; nt++){ s1loc[nt][0] = 0.f; s1loc[nt][1] = 0.f; }
    }
#pragma unroll
    for (int mt=0; mt<4; mt++){
#pragma unroll
        for (int nt=0; nt<4; nt++){
            int r  = m0 + wr*64 + mt*16 + g;
            int cc = n0 + wc*32 + nt*8 + tig*2;
            float bx = bias[cc], by = bias[cc+1];
#pragma unroll
            for (int h=0; h<2; h++){
                int row = r + 8*h;
                float v0 = acc[mt][nt][2*h+0] + bx;
                float v1 = acc[mt][nt][2*h+1] + by;
                if (EPI == 1){
                    float g0 = gelu_exact(v0), g1 = gelu_exact(v1);
                    __half2 hv = __floats2half2_rn(g0, g1);
                    *(uint32_t*)((__half*)Cout + (size_t)row*N + cc) = *(uint32_t*)&hv;
                } else {
                    if (EPI == 2){
                        const float2 rr = *(const float2*)(resid + (size_t)row*N + cc);
                        v0 += rr.x; v1 += rr.y;
                    }
                    if (EPI == 3){
                        float wgt = rsqrtf((float)((row & (Sv-1)) + 1));
                        s1loc[nt][0] += wgt * v0;
                        s1loc[nt][1] += wgt * v1;
                    }
                    float2 o; o.x = v0; o.y = v1;
                    *(float2*)((float*)Cout + (size_t)row*N + cc) = o;
                }
            }
        }
    }
    if (EPI == 3){
        // sum over g (rows): lanes differ in bits 2..4
#pragma unroll
        for (int nt=0; nt<4; nt++)
#pragma unroll
            for (int j=0; j<2; j++){
                float v = s1loc[nt][j];
                v += __shfl_xor_sync(0xffffffffu, v, 4);
                v += __shfl_xor_sync(0xffffffffu, v, 8);
                v += __shfl_xor_sync(0xffffffffu, v, 16);
                s1loc[nt][j] = v;
            }
        if (lane < 4){
            int b = m0 >> 12;                       // / Sv
            int chunk = ((m0 & (Sv-1)) >> 6) + wr;  // 64-row chunk, wr band
            size_t base = (size_t)(b*CHUNKS + chunk)*Dv;
#pragma unroll
            for (int nt=0; nt<4; nt++){
                int col = n0 + wc*32 + nt*8 + tig*2;
                s1out[base + col    ] = s1loc[nt][0] * expf(lsc[col]);
                s1out[base + col + 1] = s1loc[nt][1] * expf(lsc[col+1]);
            }
        }
    }
}

// ---------------- tiny chunk-prefix scans ------------------------------------
__global__ __launch_bounds__(256)
void k_scan1()
{
    int idx = blockIdx.x * 256 + threadIdx.x;       // 0..Bv*Dv-1
    int b = idx >> 10, d = idx & (Dv-1);
    float run = 0.f;
#pragma unroll 8
    for (int c = 0; c < CHUNKS; c++){
        int o = (b*CHUNKS + c)*Dv + d;
        g_s1p[o] = run;
        run += g_s1[o];
    }
}

__global__ __launch_bounds__(256)
void k_scan2()
{
    int idx = blockIdx.x * 256 + threadIdx.x;
    int b = idx >> 10, d = idx & (Dv-1);
    float rr = 0.f, ri = 0.f;
#pragma unroll 8
    for (int c = 0; c < CHUNKS; c++){
        int o = (b*CHUNKS + c)*Dv + d;
        g_s2rp[o] = rr; rr += g_s2r[o];
        g_s2ip[o] = ri; ri += g_s2i[o];
    }
}

// ---------------- scan pass: phi, sincos, content (fp32 out), chunk sums -----
__global__ __launch_bounds__(256)
void k_phase(const __half* __restrict__ xh, const float* __restrict__ omega,
             const float* __restrict__ log_scale)
{
    int d = blockIdx.x * blockDim.x + threadIdx.x;
    int c = blockIdx.y, b = blockIdx.z;
    float sc = expf(log_scale[d]);
    int si0 = (b*CHUNKS + c)*Dv + d;
    float phi = g_s1p[si0];
    int t0 = c * CLEN;
    size_t base  = (size_t)(b*Sv + t0)*Dv + d;
    size_t base4 = (size_t)(b*Sv + t0)*(4*Dv) + d;
    float sumR = 0.f, sumI = 0.f;
    for (int i=0; i<CLEN; i++){
        float om = omega[base + (size_t)i*Dv];
        phi += om * sc * rsqrtf((float)(t0 + i + 1));
        float s, cv; __sincosf(phi, &s, &cv);
        float xv = __half2float(xh[base + (size_t)i*Dv]);
        float cr = xv*cv, ci = xv*s;
        sumR += cr; sumI += ci;
        g_ctx[base4 + (size_t)i*4*Dv        ] = cr;
        g_ctx[base4 + (size_t)i*4*Dv +   Dv ] = ci;
    }
    g_s2r[si0] = sumR;
    g_s2i[si0] = sumI;
}

// ---------------- scan pass: running memory + retrieved (fp32 out) -----------
__global__ __launch_bounds__(256)
void k_retrieve(const __half* __restrict__ xh, const float* __restrict__ omega,
                const float* __restrict__ log_scale)
{
    int d = blockIdx.x * blockDim.x + threadIdx.x;
    int c = blockIdx.y, b = blockIdx.z;
    float sc = expf(log_scale[d]);
    int si0 = (b*CHUNKS + c)*Dv + d;
    float phi = g_s1p[si0];
    float aR  = g_s2rp[si0];
    float aI  = g_s2ip[si0];
    int t0 = c * CLEN;
    size_t base  = (size_t)(b*Sv + t0)*Dv + d;
    size_t base4 = (size_t)(b*Sv + t0)*(4*Dv) + d;
    for (int i=0; i<CLEN; i++){
        float om = omega[base + (size_t)i*Dv];
        phi += om * sc * rsqrtf((float)(t0 + i + 1));
        float s, cv; __sincosf(phi, &s, &cv);
        float xv = __half2float(xh[base + (size_t)i*Dv]);
        float cr = xv*cv, ci = xv*s;
        aR += cr; aI += ci;
        float inv = 1.0f / (float)(t0 + i + 1);
        float mr = aR*inv, mi = aI*inv;
        g_ctx[base4 + (size_t)i*4*Dv + 2*Dv] = mr*cv + mi*s;
        g_ctx[base4 + (size_t)i*4*Dv + 3*Dv] = mi*cv - mr*s;
    }
}

// ---------------- layernorm over 4096 features, fp32 in -> half out ----------
__global__ __launch_bounds__(256)
void k_layernorm(const float* __restrict__ gamma, const float* __restrict__ beta,
                 __half* __restrict__ outh)
{
    const int F = 4*Dv;
    const float* p = g_ctx + (size_t)blockIdx.x * F;
    __half* ph = outh + (size_t)blockIdx.x * F;
    const int tid = threadIdx.x;
    float4 v[4];
    float s = 0.f, q = 0.f;
#pragma unroll
    for (int j=0; j<4; j++){
        v[j] = ((const float4*)p)[tid + j*256];
        s += v[j].x + v[j].y + v[j].z + v[j].w;
        q += v[j].x*v[j].x + v[j].y*v[j].y + v[j].z*v[j].z + v[j].w*v[j].w;
    }
#pragma unroll
    for (int o=16; o>0; o>>=1){
        s += __shfl_xor_sync(0xffffffffu, s, o);
        q += __shfl_xor_sync(0xffffffffu, q, o);
    }
    __shared__ float ss[8], qq[8];
    int lane = tid & 31, wid = tid >> 5;
    if (lane == 0){ ss[wid] = s; qq[wid] = q; }
    __syncthreads();
    if (tid == 0){
        float ts = 0.f, tq = 0.f;
        for (int i=0;i<8;i++){ ts += ss[i]; tq += qq[i]; }
        ss[0] = ts; qq[0] = tq;
    }
    __syncthreads();
    float mu  = ss[0] * (1.0f / F);
    float var = qq[0] * (1.0f / F) - mu*mu;
    float rs  = rsqrtf(var + 1e-5f);
#pragma unroll
    for (int j=0; j<4; j++){
        int vi = tid + j*256;
        float4 gm = ((const float4*)gamma)[vi];
        float4 bt = ((const float4*)beta)[vi];
        __half2 h0 = __floats2half2_rn((v[j].x - mu)*rs*gm.x + bt.x,
                                       (v[j].y - mu)*rs*gm.y + bt.y);
        __half2 h1 = __floats2half2_rn((v[j].z - mu)*rs*gm.z + bt.z,
                                       (v[j].w - mu)*rs*gm.w + bt.w);
        uint2 u; u.x = *(uint32_t*)&h0; u.y = *(uint32_t*)&h1;
        ((uint2*)ph)[vi] = u;
    }
}

// ---------------- launch ----------------------------------------------------
extern "C" void kernel_launch(void* const* d_in, const int* in_sizes, int n_in,
                              void* d_out, int out_size)
{
    (void)in_sizes; (void)n_in; (void)out_size;
    const float* x         = (const float*)d_in[0];
    const float* W_omega   = (const float*)d_in[1];
    const float* b_omega   = (const float*)d_in[2];
    const float* log_scale = (const float*)d_in[3];
    const float* ln_gamma  = (const float*)d_in[4];
    const float* ln_beta   = (const float*)d_in[5];
    const float* W1        = (const float*)d_in[6];
    const float* b1        = (const float*)d_in[7];
    const float* W2        = (const float*)d_in[8];
    const float* b2        = (const float*)d_in[9];
    float* out = (float*)d_out;

    void* p;
    cudaGetSymbolAddress(&p, g_omega); float*  omega = (float*)p;
    cudaGetSymbolAddress(&p, g_ctxh);  __half* ctxh  = (__half*)p;
    cudaGetSymbolAddress(&p, g_h1h);   __half* h1h   = (__half*)p;
    cudaGetSymbolAddress(&p, g_xh);    __half* xh    = (__half*)p;
    cudaGetSymbolAddress(&p, g_w0h);   __half* w0h   = (__half*)p;
    cudaGetSymbolAddress(&p, g_w1h);   __half* w1h   = (__half*)p;
    cudaGetSymbolAddress(&p, g_w2h);   __half* w2h   = (__half*)p;
    cudaGetSymbolAddress(&p, g_s1);    float*  s1    = (float*)p;

    static bool attr_done = false;
    if (!attr_done){
        cudaFuncSetAttribute(k_gemmh<1>, cudaFuncAttributeMaxDynamicSharedMemorySize, GEMM_SMEM);
        cudaFuncSetAttribute(k_gemmh<2>, cudaFuncAttributeMaxDynamicSharedMemorySize, GEMM_SMEM);
        cudaFuncSetAttribute(k_gemmh<3>, cudaFuncAttributeMaxDynamicSharedMemorySize, GEMM_SMEM);
        attr_done = true;
    }

    dim3 blk256(256);

    // convert GEMM operands to fp16
    {
        int n4;
        n4 = (MROWS*Dv)/4;     k_tohalf<<<(n4+255)/256, blk256>>>(x,       xh,  n4);
        n4 = (Dv*Dv)/4;        k_tohalf<<<(n4+255)/256, blk256>>>(W_omega, w0h, n4);
        n4 = (4*Dv*2*Dv)/4;    k_tohalf<<<(n4+255)/256, blk256>>>(W1,      w1h, n4);
        n4 = (2*Dv*Dv)/4;      k_tohalf<<<(n4+255)/256, blk256>>>(W2,      w2h, n4);
    }

    // GEMM1 (EPI=3): omega = xh @ w0h + b_omega -> fp32, plus chunk sums g_s1
    dim3 gg1(Dv/128, MROWS/128);
    k_gemmh<3><<<gg1, blk256, GEMM_SMEM>>>(xh, w0h, b_omega, nullptr, omega,
                                           MROWS, Dv, Dv, s1, log_scale);

    // chunk-prefix of s1, then phase, then prefix of s2, then retrieve
    k_scan1<<<(Bv*Dv)/256, blk256>>>();
    dim3 gs(Dv/256, CHUNKS, Bv);
    k_phase<<<gs, blk256>>>(xh, omega, log_scale);
    k_scan2<<<(Bv*Dv)/256, blk256>>>();
    k_retrieve<<<gs, blk256>>>(xh, omega, log_scale);

    // layernorm: g_ctx (fp32) -> ctxh (half)
    k_layernorm<<<MROWS, blk256>>>(ln_gamma, ln_beta, ctxh);

    // GEMM2: h1h = gelu(ctxh @ w1h + b1)  (16384 x 2048 x 4096) -> half
    dim3 gg2((2*Dv)/128, MROWS/128);
    k_gemmh<1><<<gg2, blk256, GEMM_SMEM>>>(ctxh, w1h, b1, nullptr, h1h,
                                           MROWS, 2*Dv, 4*Dv, nullptr, nullptr);

    // GEMM3: out = h1h @ w2h + b2 + x     (16384 x 1024 x 2048) -> fp32
    dim3 gg3(Dv/128, MROWS/128);
    k_gemmh<2><<<gg3, blk256, GEMM_SMEM>>>(h1h, w2h, b2, x, out,
                                           MROWS, Dv, 2*Dv, nullptr, nullptr);
}